// round 3
// baseline (speedup 1.0000x reference)
#include <cuda_runtime.h>
#include <cstdint>

// HalftoneMARLLoss — fully fused single-kernel analytic single-flip formulation.
//
// Identities (validated in round 1, rel_err 2.3e-6):
//  * candidates are rank-1 perturbations of the sampled h (delta in {-1,0,+1})
//  * conv(h'^2) == conv(h') exactly (h' is binary in fp32)
//  * c-side maps are candidate-independent
//  * loss = -( S_0 + S_1 + (sum_flips pi*dT)/1024 ) / 2048
//
// Fusion: grid of 66 blocks, one wave (<=148 SMs) -> spin-wait is safe.
//   blocks 0,1   : base maps + S_b for image b; release g_ready
//   blocks 2..65 : acquire-spin on g_ready; 32 flip candidates each (1 warp per
//                  candidate, 121-tap window from staged shared maps)
//   last-done flip block: deterministic final reduction, writes out,
//                  RESETS flags (device globals persist across graph replays).

#define HW 1024
#define WS_F 0.06f
#define C1_F 1e-4f
#define C2_F 9e-4f
#define EPS_F 1e-12f

// Normalized Gaussian (sigma=2, size 11) as compile-time constants.
#define GSUM 4.9859044930311974
#define GW0 ((float)(0.0439369336234074 / GSUM))
#define GW1 ((float)(0.1353352832366127 / GSUM))
#define GW2 ((float)(0.3246524673583497 / GSUM))
#define GW3 ((float)(0.6065306597126334 / GSUM))
#define GW4 ((float)(0.8824969025845955 / GSUM))
#define GW5 ((float)(1.0 / GSUM))
#define GW_TABLE {GW0, GW1, GW2, GW3, GW4, GW5, GW4, GW3, GW2, GW1, GW0}

// scratch (static device globals — no allocations)
__device__ float g_muh[2 * HW], g_muc[2 * HW], g_hc[2 * HW];
__device__ float g_sigc[2 * HW], g_wsc[2 * HW], g_U0[2 * HW];
__device__ float g_h[2 * HW];
__device__ float g_S[2];
__device__ float g_part[64];
__device__ int g_ready;   // zero-init; reset by last block each launch
__device__ int g_done;

__device__ __forceinline__ int ld_acquire_gpu(const int* p) {
    int v;
    asm volatile("ld.acquire.gpu.s32 %0, [%1];" : "=r"(v) : "l"(p) : "memory");
    return v;
}

__device__ __forceinline__ void tf_round(uint32_t& x0, uint32_t& x1, int r) {
    x0 += x1;
    x1 = (x1 << r) | (x1 >> (32 - r));
    x1 ^= x0;
}

__device__ __forceinline__ void threefry2x32(uint32_t k0, uint32_t k1,
                                             uint32_t& x0, uint32_t& x1) {
    uint32_t ks2 = k0 ^ k1 ^ 0x1BD11BDAu;
    x0 += k0; x1 += k1;
    tf_round(x0, x1, 13); tf_round(x0, x1, 15); tf_round(x0, x1, 26); tf_round(x0, x1, 6);
    x0 += k1; x1 += ks2 + 1u;
    tf_round(x0, x1, 17); tf_round(x0, x1, 29); tf_round(x0, x1, 16); tf_round(x0, x1, 24);
    x0 += ks2; x1 += k0 + 2u;
    tf_round(x0, x1, 13); tf_round(x0, x1, 15); tf_round(x0, x1, 26); tf_round(x0, x1, 6);
    x0 += k0; x1 += k1 + 3u;
    tf_round(x0, x1, 17); tf_round(x0, x1, 29); tf_round(x0, x1, 16); tf_round(x0, x1, 24);
    x0 += k1; x1 += ks2 + 4u;
    tf_round(x0, x1, 13); tf_round(x0, x1, 15); tf_round(x0, x1, 26); tf_round(x0, x1, 6);
    x0 += ks2; x1 += k0 + 5u;
}

__device__ __forceinline__ float jax_uniform_elem(int e) {
    uint32_t x0 = 0u, x1 = (uint32_t)e;
    threefry2x32(0u, 42u, x0, x1);
    uint32_t bits = x0 ^ x1;
    float f = __uint_as_float((bits >> 9) | 0x3f800000u) - 1.0f;
    return fmaxf(f, 0.0f);
}

__global__ __launch_bounds__(1024) void k_fused(const float* __restrict__ prob,
                                                const float* __restrict__ cin,
                                                float* __restrict__ out) {
    // padded shared tiles: A* are x-padded (width 42, valid x at +5),
    // T* are y-padded (42 rows, valid y at +5, width 32)
    __shared__ float A0[32 * 42], A1[32 * 42], A2[32 * 42], A3[32 * 42];
    __shared__ float T0[42 * 32], T1[42 * 32], T2[42 * 32], T3[42 * 32];
    __shared__ float red[32];
    __shared__ int s_last;

    const float GW_[11] = GW_TABLE;   // local const table -> folds to immediates

    const int tid = threadIdx.x;
    const int blk = blockIdx.x;

    if (blk < 2) {
        // ================= BASE PHASE (2 blocks, one image each) =============
        const int b = blk;
        const int p = tid;
        const int y = p >> 5, x = p & 31;

        // zero only the pad regions (320 elements per array family)
        if (tid < 320) {
            int r = tid / 10, cc = tid % 10;
            int col = (cc < 5) ? cc : cc + 32;
            int i = r * 42 + col;
            A0[i] = 0.f; A1[i] = 0.f; A2[i] = 0.f; A3[i] = 0.f;
            int r2 = tid >> 5;
            int row = (r2 < 5) ? r2 : r2 + 32;
            int i2 = row * 32 + (tid & 31);
            T0[i2] = 0.f; T1[i2] = 0.f; T2[i2] = 0.f; T3[i2] = 0.f;
        }

        const int e = b * HW + p;
        float h = (jax_uniform_elem(e) < prob[e]) ? 1.f : 0.f;
        float cv = cin[e];
        g_h[e] = h;

        const int ai = y * 42 + x + 5;
        const int ti = (y + 5) * 32 + x;
        A0[ai] = h; A1[ai] = cv; A2[ai] = h * cv; A3[ai] = cv * cv;
        __syncthreads();

        // horizontal pass (no predicates: pads are zero)
        const float* a0 = &A0[y * 42 + x];
        const float* a1 = &A1[y * 42 + x];
        const float* a2 = &A2[y * 42 + x];
        const float* a3 = &A3[y * 42 + x];
        float s0 = 0.f, s1 = 0.f, s2 = 0.f, s3 = 0.f;
#pragma unroll
        for (int j = 0; j < 11; j++) {
            float w = GW_[j];
            s0 += w * a0[j]; s1 += w * a1[j]; s2 += w * a2[j]; s3 += w * a3[j];
        }
        T0[ti] = s0; T1[ti] = s1; T2[ti] = s2; T3[ti] = s3;
        __syncthreads();

        // vertical pass
        const float* t0 = &T0[y * 32 + x];
        const float* t1 = &T1[y * 32 + x];
        const float* t2 = &T2[y * 32 + x];
        const float* t3 = &T3[y * 32 + x];
        float muh = 0.f, muc = 0.f, hcv = 0.f, c2v = 0.f;
#pragma unroll
        for (int j = 0; j < 11; j++) {
            float w = GW_[j];
            muh += w * t0[j * 32]; muc += w * t1[j * 32];
            hcv += w * t2[j * 32]; c2v += w * t3[j * 32];
        }

        // stage 2: c_var = conv((c - mu_c)^2)
        float dcm = cv - muc;
        A0[ai] = dcm * dcm;
        __syncthreads();
        float sH = 0.f;
#pragma unroll
        for (int j = 0; j < 11; j++) sH += GW_[j] * a0[j];
        T0[ti] = sH;
        __syncthreads();
        float cvar = 0.f;
#pragma unroll
        for (int j = 0; j < 11; j++) cvar += GW_[j] * t0[j * 32];

        // per-pixel base reward
        float sigh = muh - muh * muh;          // conv(h^2)==conv(h), h binary
        float sigc = c2v - muc * muc;
        float sighc = hcv - muh * muc;
        float xv = fmaxf(sigh * sigc, 0.f) + EPS_F;
        float sq = xv * rsqrtf(xv);
        float num = (2.f * muh * muc + C1_F) * (2.f * sq + C2_F) * (2.f * sighc + C2_F);
        float den = (muh * muh + muc * muc + C1_F) * (sigh + sigc + C2_F) * (sq + C2_F + EPS_F);
        float ssim = __fdividef(num, den);
        float cc2 = cvar + EPS_F;
        float ccon = fminf(2.f * (cc2 * rsqrtf(cc2)), 1.f);
        float wsc = WS_F * ccon;
        float dmh = muh - muc;
        float U0 = wsc * ssim - dmh * dmh;
        float Tb = U0 + WS_F - wsc;

        g_muh[e] = muh; g_muc[e] = muc; g_hc[e] = hcv;
        g_sigc[e] = sigc; g_wsc[e] = wsc; g_U0[e] = U0;

        // block reduce sum(Tb) -> g_S[b]
        float v = Tb;
#pragma unroll
        for (int o = 16; o; o >>= 1) v += __shfl_xor_sync(0xffffffffu, v, o);
        if ((p & 31) == 0) red[p >> 5] = v;
        __syncthreads();
        if (p < 32) {
            float w2 = red[p];
#pragma unroll
            for (int o = 16; o; o >>= 1) w2 += __shfl_xor_sync(0xffffffffu, w2, o);
            if (p == 0) g_S[b] = w2;
        }

        // release: all stores device-visible, then bump flag
        __threadfence();
        __syncthreads();
        if (tid == 0) atomicAdd(&g_ready, 1);
    } else {
        // ================= FLIP PHASE (64 blocks x 32 candidates) ============
        const int f = blk - 2;            // 0..63
        const int b = f >> 5;
        const int y0 = f & 31;            // all candidates share row y0

        if (tid == 0) {
            while (ld_acquire_gpu(&g_ready) < 2) __nanosleep(64);
        }
        __syncthreads();
        __threadfence();

        // stage the 11x32 map window into shared (6 maps)
        float* Mmuc = A0; float* Mmuh = A1; float* Mhc = A2;
        float* Msigc = A3; float* Mwsc = T0; float* MU0 = T1;
        if (tid < 352) {
            int r = tid >> 5, colx = tid & 31;
            int yy = y0 + r - 5;
            if ((unsigned)yy < 32u) {
                int q = b * HW + yy * 32 + colx;
                Mmuc[tid] = g_muc[q]; Mmuh[tid] = g_muh[q]; Mhc[tid] = g_hc[q];
                Msigc[tid] = g_sigc[q]; Mwsc[tid] = g_wsc[q]; MU0[tid] = g_U0[q];
            }
        }
        __syncthreads();

        const int w = tid >> 5;           // warp index = candidate x
        const int lane = tid & 31;
        const int gw = f * 32 + w;        // == b*1024 + y0*32 + x

        float h = g_h[gw];
        float delta = 1.f - 2.f * h;
        float pa = prob[gw];
        float pi = (h == 0.f) ? pa : (1.f - pa);
        float dca = delta * cin[gw];

        float dacc = 0.f;
#pragma unroll
        for (int t = lane; t < 121; t += 32) {
            int r = t / 11;
            int cidx = t - r * 11;
            int yy = y0 + r - 5;
            int xx = w + cidx - 5;
            if (((unsigned)yy < 32u) & ((unsigned)xx < 32u)) {
                float wt = GW_[r] * GW_[cidx];
                int s = r * 32 + xx;
                float muc = Mmuc[s];
                float muh = Mmuh[s] + delta * wt;
                float sigc = Msigc[s];
                float sighc = Mhc[s] + dca * wt - muh * muc;
                float sigh = muh - muh * muh;
                float xv = fmaxf(sigh * sigc, 0.f) + EPS_F;
                float sq = xv * rsqrtf(xv);
                float num = (2.f * muh * muc + C1_F) * (2.f * sq + C2_F) * (2.f * sighc + C2_F);
                float den = (muh * muh + muc * muc + C1_F) * (sigh + sigc + C2_F) * (sq + C2_F + EPS_F);
                float dmh = muh - muc;
                float Un = Mwsc[s] * __fdividef(num, den) - dmh * dmh;
                dacc += Un - MU0[s];
            }
        }
#pragma unroll
        for (int o = 16; o; o >>= 1) dacc += __shfl_xor_sync(0xffffffffu, dacc, o);
        if (lane == 0) red[w] = pi * dacc;
        __syncthreads();

        if (tid == 0) {
            float s = 0.f;
#pragma unroll
            for (int i = 0; i < 32; i++) s += red[i];
            g_part[f] = s;
            __threadfence();
            int t = atomicAdd(&g_done, 1);
            s_last = (t == 63) ? 1 : 0;
        }
        __syncthreads();

        if (s_last) {
            // last block: deterministic final reduction
            __threadfence();
            float v = (tid < 64) ? g_part[tid] : 0.f;
#pragma unroll
            for (int o = 16; o; o >>= 1) v += __shfl_xor_sync(0xffffffffu, v, o);
            if (tid == 0) red[0] = v;
            if (tid == 32) red[1] = v;
            __syncthreads();
            if (tid == 0) {
                float A = red[0] + red[1];
                out[0] = -(g_S[0] + g_S[1] + A * (1.0f / 1024.0f)) * (1.0f / 2048.0f);
                g_ready = 0;   // reset for the next graph replay
                g_done = 0;
            }
        }
    }
}

extern "C" void kernel_launch(void* const* d_in, const int* in_sizes, int n_in,
                              void* d_out, int out_size) {
    const float* prob = (const float*)d_in[0];
    const float* c = (const float*)d_in[1];
    // d_in[2] (z) is unused by the reference.
    float* out = (float*)d_out;
    k_fused<<<66, 1024>>>(prob, c, out);
}

// round 4
// speedup vs baseline: 1.3455x; 1.3455x over previous
#include <cuda_runtime.h>
#include <cstdint>

// HalftoneMARLLoss — redundant-base fused kernel.
//
// 128 independent blocks (1 wave). Block i: image b=i>>6, row y0=(i&63)>>1,
// half xh=i&1. Every block redundantly computes the FULL base maps for its
// image in shared memory (~200 instr/thread), then evaluates its 16 flip
// candidates (2 warps each) straight out of smem. No inter-block ordering
// except a last-done-block final reduction. Math identical to the validated
// round-1/3 formulation (rel_err ~2e-6).

#define HW 1024
#define WS_F 0.06f
#define C1_F 1e-4f
#define C2_F 9e-4f
#define EPS_F 1e-12f

#define GSUM 4.9859044930311974
#define GW0 ((float)(0.0439369336234074 / GSUM))
#define GW1 ((float)(0.1353352832366127 / GSUM))
#define GW2 ((float)(0.3246524673583497 / GSUM))
#define GW3 ((float)(0.6065306597126334 / GSUM))
#define GW4 ((float)(0.8824969025845955 / GSUM))
#define GW5 ((float)(1.0 / GSUM))
#define GW_TABLE {GW0, GW1, GW2, GW3, GW4, GW5, GW4, GW3, GW2, GW1, GW0}

__device__ float g_S[2];
__device__ float g_part[128];
__device__ int g_done;   // zero-init; reset by last block each launch

__device__ __forceinline__ void tf_round(uint32_t& x0, uint32_t& x1, int r) {
    x0 += x1;
    x1 = (x1 << r) | (x1 >> (32 - r));
    x1 ^= x0;
}

__device__ __forceinline__ float jax_uniform_elem(int e) {
    // JAX threefry2x32, key(42)=(0,42), partitionable: bits = x0^x1 of TF(0, e)
    const uint32_t k0 = 0u, k1 = 42u, ks2 = k0 ^ k1 ^ 0x1BD11BDAu;
    uint32_t x0 = 0u, x1 = (uint32_t)e;
    x0 += k0; x1 += k1;
    tf_round(x0, x1, 13); tf_round(x0, x1, 15); tf_round(x0, x1, 26); tf_round(x0, x1, 6);
    x0 += k1; x1 += ks2 + 1u;
    tf_round(x0, x1, 17); tf_round(x0, x1, 29); tf_round(x0, x1, 16); tf_round(x0, x1, 24);
    x0 += ks2; x1 += k0 + 2u;
    tf_round(x0, x1, 13); tf_round(x0, x1, 15); tf_round(x0, x1, 26); tf_round(x0, x1, 6);
    x0 += k0; x1 += k1 + 3u;
    tf_round(x0, x1, 17); tf_round(x0, x1, 29); tf_round(x0, x1, 16); tf_round(x0, x1, 24);
    x0 += k1; x1 += ks2 + 4u;
    tf_round(x0, x1, 13); tf_round(x0, x1, 15); tf_round(x0, x1, 26); tf_round(x0, x1, 6);
    x0 += ks2; x1 += k0 + 5u;
    uint32_t bits = x0 ^ x1;
    float f = __uint_as_float((bits >> 9) | 0x3f800000u) - 1.0f;
    return fmaxf(f, 0.0f);
}

__global__ __launch_bounds__(1024) void k_all(const float* __restrict__ prob,
                                              const float* __restrict__ cin,
                                              float* __restrict__ out) {
    // A*: x-padded tiles (32 rows x 42, valid x at +5)
    // T*: y-padded tiles (42 rows x 32, valid y at +5)
    // After the base conv phases, tiles are overlaid with full-image maps [p]:
    //   A1=muh, A2=muc, A3=hc, T1=sigc, T2=wsc, T3=U0
    __shared__ float A0[1344], A1[1344], A2[1344], A3[1344];
    __shared__ float T0[1344], T1[1344], T2[1344], T3[1344];
    __shared__ float Hrow[32], red[32], Pi[16];

    const float GW_[11] = GW_TABLE;

    const int i = blockIdx.x;
    const int tid = threadIdx.x;
    const int b = i >> 6;
    const int hr = i & 63;
    const int y0 = hr >> 1;
    const int xh = hr & 1;
    const int y = tid >> 5, x = tid & 31;
    const int e = b * HW + tid;

    // zero pad regions (320 elems per tile family)
    if (tid < 320) {
        int r = tid / 10, cc = tid % 10;
        int col = (cc < 5) ? cc : cc + 32;
        int ia = r * 42 + col;
        A0[ia] = 0.f; A1[ia] = 0.f; A2[ia] = 0.f; A3[ia] = 0.f;
        int r2 = tid >> 5;
        int row = (r2 < 5) ? r2 : r2 + 32;
        int it = row * 32 + (tid & 31);
        T0[it] = 0.f; T1[it] = 0.f; T2[it] = 0.f; T3[it] = 0.f;
    }

    // ---------------- base maps (full image, redundant per block) ----------
    float h = (jax_uniform_elem(e) < prob[e]) ? 1.f : 0.f;
    float cv = cin[e];
    if (y == y0) Hrow[x] = h;

    const int ai = y * 42 + x + 5;
    const int ti = (y + 5) * 32 + x;
    A0[ai] = h; A1[ai] = cv; A2[ai] = h * cv; A3[ai] = cv * cv;
    __syncthreads();

    {   // horizontal pass (pads are zero -> no predicates)
        const float* a0 = &A0[y * 42 + x];
        const float* a1 = &A1[y * 42 + x];
        const float* a2 = &A2[y * 42 + x];
        const float* a3 = &A3[y * 42 + x];
        float s0 = 0.f, s1 = 0.f, s2 = 0.f, s3 = 0.f;
#pragma unroll
        for (int j = 0; j < 11; j++) {
            float w = GW_[j];
            s0 += w * a0[j]; s1 += w * a1[j]; s2 += w * a2[j]; s3 += w * a3[j];
        }
        T0[ti] = s0; T1[ti] = s1; T2[ti] = s2; T3[ti] = s3;
    }
    __syncthreads();

    float muh = 0.f, muc = 0.f, hcv = 0.f, c2v = 0.f;
    {   // vertical pass
        const float* t0 = &T0[y * 32 + x];
        const float* t1 = &T1[y * 32 + x];
        const float* t2 = &T2[y * 32 + x];
        const float* t3 = &T3[y * 32 + x];
#pragma unroll
        for (int j = 0; j < 11; j++) {
            float w = GW_[j];
            muh += w * t0[j * 32]; muc += w * t1[j * 32];
            hcv += w * t2[j * 32]; c2v += w * t3[j * 32];
        }
    }
    __syncthreads();   // all T reads done -> A1..A3, T1..T3 reusable

    float sigc = c2v - muc * muc;
    float dcm = cv - muc;
    A1[tid] = muh; A2[tid] = muc; A3[tid] = hcv; T1[tid] = sigc;
    A0[ai] = dcm * dcm;
    __syncthreads();

    {   // c_var horizontal
        const float* a0 = &A0[y * 42 + x];
        float sH = 0.f;
#pragma unroll
        for (int j = 0; j < 11; j++) sH += GW_[j] * a0[j];
        T0[ti] = sH;
    }
    __syncthreads();

    float cvar = 0.f;
    {   // c_var vertical
        const float* t0 = &T0[y * 32 + x];
#pragma unroll
        for (int j = 0; j < 11; j++) cvar += GW_[j] * t0[j * 32];
    }

    // per-pixel base reward
    float sigh = muh - muh * muh;            // conv(h^2)==conv(h), h binary
    float sighc = hcv - muh * muc;
    float xv = fmaxf(sigh * sigc, 0.f) + EPS_F;
    float sq = xv * rsqrtf(xv);
    float num = (2.f * muh * muc + C1_F) * (2.f * sq + C2_F) * (2.f * sighc + C2_F);
    float den = (muh * muh + muc * muc + C1_F) * (sigh + sigc + C2_F) * (sq + C2_F + EPS_F);
    float ssim = __fdividef(num, den);
    float cc2 = cvar + EPS_F;
    float ccon = fminf(2.f * (cc2 * rsqrtf(cc2)), 1.f);
    float wsc = WS_F * ccon;
    float dmh = muh - muc;
    float U0 = wsc * ssim - dmh * dmh;

    T2[tid] = wsc; T3[tid] = U0;

    // blocks 0 and 64 also produce the base sums S_b
    if (hr == 0) {
        float Tb = U0 + WS_F - wsc;
        float v = Tb;
#pragma unroll
        for (int o = 16; o; o >>= 1) v += __shfl_xor_sync(0xffffffffu, v, o);
        if ((tid & 31) == 0) red[tid >> 5] = v;
        __syncthreads();
        if (tid < 32) {
            float w2 = red[tid];
#pragma unroll
            for (int o = 16; o; o >>= 1) w2 += __shfl_xor_sync(0xffffffffu, w2, o);
            if (tid == 0) g_S[b] = w2;
        }
    }
    __syncthreads();   // M maps (A1..A3,T1..T3) + Hrow ready for flip phase

    // ---------------- flip phase: 16 candidates, 2 warps each -------------
    const int wid = tid >> 5;
    const int lane = tid & 31;
    const int cand = xh * 16 + (wid >> 1);   // candidate x in row y0
    const int half = wid & 1;                // which half of the 121 window

    const int aidx = b * HW + y0 * 32 + cand;
    float hA = Hrow[cand];
    float delta = 1.f - 2.f * hA;
    float pa = prob[aidx];
    float pii = (hA == 0.f) ? pa : (1.f - pa);
    float dca = delta * cin[aidx];

    float dacc = 0.f;
#pragma unroll
    for (int k = 0; k < 2; k++) {
        int t = half * 64 + k * 32 + lane;
        if (t < 121) {
            int r = t / 11;
            int cidx = t - r * 11;
            int yy = y0 + r - 5;
            int xx = cand + cidx - 5;
            if (((unsigned)yy < 32u) & ((unsigned)xx < 32u)) {
                float wt = GW_[r] * GW_[cidx];
                int q = yy * 32 + xx;
                float muc2 = A2[q];
                float muh2 = A1[q] + delta * wt;
                float sigc2 = T1[q];
                float sighc2 = A3[q] + dca * wt - muh2 * muc2;
                float sigh2 = muh2 - muh2 * muh2;
                float xv2 = fmaxf(sigh2 * sigc2, 0.f) + EPS_F;
                float sq2 = xv2 * rsqrtf(xv2);
                float n2 = (2.f * muh2 * muc2 + C1_F) * (2.f * sq2 + C2_F) * (2.f * sighc2 + C2_F);
                float d2 = (muh2 * muh2 + muc2 * muc2 + C1_F) * (sigh2 + sigc2 + C2_F) * (sq2 + C2_F + EPS_F);
                float dmh2 = muh2 - muc2;
                float Un = T2[q] * __fdividef(n2, d2) - dmh2 * dmh2;
                dacc += Un - T3[q];
            }
        }
    }
#pragma unroll
    for (int o = 16; o; o >>= 1) dacc += __shfl_xor_sync(0xffffffffu, dacc, o);
    if (lane == 0) {
        red[wid] = dacc;
        if (half == 0) Pi[wid >> 1] = pii;
    }
    __syncthreads();

    if (tid < 16) {
        float cs = (red[2 * tid] + red[2 * tid + 1]) * Pi[tid];
#pragma unroll
        for (int o = 8; o; o >>= 1) cs += __shfl_down_sync(0xffffu, cs, o);
        if (tid == 0) {
            g_part[i] = cs;
            __threadfence();
            int t = atomicAdd(&g_done, 1);
            red[0] = (t == 127) ? 1.f : 0.f;
        }
    }
    __syncthreads();

    if (red[0] != 0.f) {
        // last-done block: deterministic final reduction over 128 partials
        __threadfence();
        if (tid < 128) {
            float v = g_part[tid];
#pragma unroll
            for (int o = 16; o; o >>= 1) v += __shfl_xor_sync(0xffffffffu, v, o);
            if ((tid & 31) == 0) Pi[tid >> 5] = v;  // reuse Pi as 4-slot scratch
        }
        __syncthreads();
        if (tid == 0) {
            float A = Pi[0] + Pi[1] + Pi[2] + Pi[3];
            out[0] = -(g_S[0] + g_S[1] + A * (1.0f / 1024.0f)) * (1.0f / 2048.0f);
            g_done = 0;   // reset for next graph replay
        }
    }
}

extern "C" void kernel_launch(void* const* d_in, const int* in_sizes, int n_in,
                              void* d_out, int out_size) {
    const float* prob = (const float*)d_in[0];
    const float* c = (const float*)d_in[1];
    // d_in[2] (z) is unused by the reference.
    float* out = (float*)d_out;
    k_all<<<128, 1024>>>(prob, c, out);
}

// round 5
// speedup vs baseline: 1.3490x; 1.0026x over previous
#include <cuda_runtime.h>
#include <cstdint>

// HalftoneMARLLoss — redundant-base fused kernel, round 5.
// Fix vs round 4: the Gaussian weight table was dynamically indexed in the
// flip phase, forcing the whole array into LOCAL memory and turning all 55
// statically-indexed base-conv weight reads into LDL as well (~2x instruction
// inflation, L1=23%). Now: base conv uses a fold-to-immediate local table
// (static indices only); flip phase reads a precomputed shared Wsh[121].

#define HW 1024
#define WS_F 0.06f
#define C1_F 1e-4f
#define C2_F 9e-4f
#define EPS_F 1e-12f

#define GSUM 4.9859044930311974
#define GW0 ((float)(0.0439369336234074 / GSUM))
#define GW1 ((float)(0.1353352832366127 / GSUM))
#define GW2 ((float)(0.3246524673583497 / GSUM))
#define GW3 ((float)(0.6065306597126334 / GSUM))
#define GW4 ((float)(0.8824969025845955 / GSUM))
#define GW5 ((float)(1.0 / GSUM))
#define GW_TABLE {GW0, GW1, GW2, GW3, GW4, GW5, GW4, GW3, GW2, GW1, GW0}

__constant__ float GWC[11] = GW_TABLE;

__device__ float g_S[2];
__device__ float g_part[128];
__device__ int g_done;   // zero-init; reset by last block each launch

__device__ __forceinline__ void tf_round(uint32_t& x0, uint32_t& x1, int r) {
    x0 += x1;
    x1 = (x1 << r) | (x1 >> (32 - r));
    x1 ^= x0;
}

__device__ __forceinline__ float jax_uniform_elem(int e) {
    // JAX threefry2x32, key(42)=(0,42), partitionable: bits = x0^x1 of TF(0, e)
    const uint32_t k0 = 0u, k1 = 42u, ks2 = k0 ^ k1 ^ 0x1BD11BDAu;
    uint32_t x0 = 0u, x1 = (uint32_t)e;
    x0 += k0; x1 += k1;
    tf_round(x0, x1, 13); tf_round(x0, x1, 15); tf_round(x0, x1, 26); tf_round(x0, x1, 6);
    x0 += k1; x1 += ks2 + 1u;
    tf_round(x0, x1, 17); tf_round(x0, x1, 29); tf_round(x0, x1, 16); tf_round(x0, x1, 24);
    x0 += ks2; x1 += k0 + 2u;
    tf_round(x0, x1, 13); tf_round(x0, x1, 15); tf_round(x0, x1, 26); tf_round(x0, x1, 6);
    x0 += k0; x1 += k1 + 3u;
    tf_round(x0, x1, 17); tf_round(x0, x1, 29); tf_round(x0, x1, 16); tf_round(x0, x1, 24);
    x0 += k1; x1 += ks2 + 4u;
    tf_round(x0, x1, 13); tf_round(x0, x1, 15); tf_round(x0, x1, 26); tf_round(x0, x1, 6);
    x0 += ks2; x1 += k0 + 5u;
    uint32_t bits = x0 ^ x1;
    float f = __uint_as_float((bits >> 9) | 0x3f800000u) - 1.0f;
    return fmaxf(f, 0.0f);
}

__global__ __launch_bounds__(1024) void k_all(const float* __restrict__ prob,
                                              const float* __restrict__ cin,
                                              float* __restrict__ out) {
    // A*: x-padded tiles (32 rows x 42, valid x at +5)
    // T*: y-padded tiles (42 rows x 32, valid y at +5)
    // After the base conv phases, tiles are overlaid with full-image maps [p]:
    //   A1=muh, A2=muc, A3=hc, T1=sigc, T2=wsc, T3=U0
    __shared__ float A0[1344], A1[1344], A2[1344], A3[1344];
    __shared__ float T0[1344], T1[1344], T2[1344], T3[1344];
    __shared__ float Hrow[32], red[32], Pi[16];
    __shared__ float Wsh[121];   // Gaussian outer-product table for flip phase

    // base-phase weights: STATIC indices only -> folds to FFMA immediates
    const float GW_[11] = GW_TABLE;

    const int i = blockIdx.x;
    const int tid = threadIdx.x;
    const int b = i >> 6;
    const int hr = i & 63;
    const int y0 = hr >> 1;
    const int xh = hr & 1;
    const int y = tid >> 5, x = tid & 31;
    const int e = b * HW + tid;

    // zero pad regions (320 elems per tile family); spare threads fill Wsh
    if (tid < 320) {
        int r = tid / 10, cc = tid % 10;
        int col = (cc < 5) ? cc : cc + 32;
        int ia = r * 42 + col;
        A0[ia] = 0.f; A1[ia] = 0.f; A2[ia] = 0.f; A3[ia] = 0.f;
        int r2 = tid >> 5;
        int row = (r2 < 5) ? r2 : r2 + 32;
        int it = row * 32 + (tid & 31);
        T0[it] = 0.f; T1[it] = 0.f; T2[it] = 0.f; T3[it] = 0.f;
    } else if (tid >= 512 && tid < 633) {
        int t = tid - 512;
        Wsh[t] = GWC[t / 11] * GWC[t % 11];
    }

    // ---------------- base maps (full image, redundant per block) ----------
    float h = (jax_uniform_elem(e) < prob[e]) ? 1.f : 0.f;
    float cv = cin[e];
    if (y == y0) Hrow[x] = h;

    const int ai = y * 42 + x + 5;
    const int ti = (y + 5) * 32 + x;
    A0[ai] = h; A1[ai] = cv; A2[ai] = h * cv; A3[ai] = cv * cv;
    __syncthreads();

    {   // horizontal pass (pads are zero -> no predicates)
        const float* a0 = &A0[y * 42 + x];
        const float* a1 = &A1[y * 42 + x];
        const float* a2 = &A2[y * 42 + x];
        const float* a3 = &A3[y * 42 + x];
        float s0 = 0.f, s1 = 0.f, s2 = 0.f, s3 = 0.f;
#pragma unroll
        for (int j = 0; j < 11; j++) {
            float w = GW_[j];
            s0 += w * a0[j]; s1 += w * a1[j]; s2 += w * a2[j]; s3 += w * a3[j];
        }
        T0[ti] = s0; T1[ti] = s1; T2[ti] = s2; T3[ti] = s3;
    }
    __syncthreads();

    float muh = 0.f, muc = 0.f, hcv = 0.f, c2v = 0.f;
    {   // vertical pass
        const float* t0 = &T0[y * 32 + x];
        const float* t1 = &T1[y * 32 + x];
        const float* t2 = &T2[y * 32 + x];
        const float* t3 = &T3[y * 32 + x];
#pragma unroll
        for (int j = 0; j < 11; j++) {
            float w = GW_[j];
            muh += w * t0[j * 32]; muc += w * t1[j * 32];
            hcv += w * t2[j * 32]; c2v += w * t3[j * 32];
        }
    }
    __syncthreads();   // all T reads done -> A1..A3, T1..T3 reusable

    float sigc = c2v - muc * muc;
    float dcm = cv - muc;
    A1[tid] = muh; A2[tid] = muc; A3[tid] = hcv; T1[tid] = sigc;
    A0[ai] = dcm * dcm;
    __syncthreads();

    {   // c_var horizontal
        const float* a0 = &A0[y * 42 + x];
        float sH = 0.f;
#pragma unroll
        for (int j = 0; j < 11; j++) sH += GW_[j] * a0[j];
        T0[ti] = sH;
    }
    __syncthreads();

    float cvar = 0.f;
    {   // c_var vertical
        const float* t0 = &T0[y * 32 + x];
#pragma unroll
        for (int j = 0; j < 11; j++) cvar += GW_[j] * t0[j * 32];
    }

    // per-pixel base reward
    float sigh = muh - muh * muh;            // conv(h^2)==conv(h), h binary
    float sighc = hcv - muh * muc;
    float xv = fmaxf(sigh * sigc, 0.f) + EPS_F;
    float sq = xv * rsqrtf(xv);
    float num = (2.f * muh * muc + C1_F) * (2.f * sq + C2_F) * (2.f * sighc + C2_F);
    float den = (muh * muh + muc * muc + C1_F) * (sigh + sigc + C2_F) * (sq + C2_F + EPS_F);
    float ssim = __fdividef(num, den);
    float cc2 = cvar + EPS_F;
    float ccon = fminf(2.f * (cc2 * rsqrtf(cc2)), 1.f);
    float wsc = WS_F * ccon;
    float dmh = muh - muc;
    float U0 = wsc * ssim - dmh * dmh;

    T2[tid] = wsc; T3[tid] = U0;

    // blocks 0 and 64 also produce the base sums S_b
    if (hr == 0) {
        float Tb = U0 + WS_F - wsc;
        float v = Tb;
#pragma unroll
        for (int o = 16; o; o >>= 1) v += __shfl_xor_sync(0xffffffffu, v, o);
        if ((tid & 31) == 0) red[tid >> 5] = v;
        __syncthreads();
        if (tid < 32) {
            float w2 = red[tid];
#pragma unroll
            for (int o = 16; o; o >>= 1) w2 += __shfl_xor_sync(0xffffffffu, w2, o);
            if (tid == 0) g_S[b] = w2;
        }
    }
    __syncthreads();   // M maps (A1..A3,T1..T3) + Hrow + Wsh ready

    // ---------------- flip phase: 16 candidates, 2 warps each -------------
    const int wid = tid >> 5;
    const int lane = tid & 31;
    const int cand = xh * 16 + (wid >> 1);   // candidate x in row y0
    const int half = wid & 1;                // which half of the 121 window

    const int aidx = b * HW + y0 * 32 + cand;
    float hA = Hrow[cand];
    float delta = 1.f - 2.f * hA;
    float pa = prob[aidx];
    float pii = (hA == 0.f) ? pa : (1.f - pa);
    float dca = delta * cin[aidx];

    float dacc = 0.f;
#pragma unroll
    for (int k = 0; k < 2; k++) {
        int t = half * 64 + k * 32 + lane;
        if (t < 121) {
            int r = t / 11;
            int cidx = t - r * 11;
            int yy = y0 + r - 5;
            int xx = cand + cidx - 5;
            if (((unsigned)yy < 32u) & ((unsigned)xx < 32u)) {
                float wt = Wsh[t];
                int q = yy * 32 + xx;
                float muc2 = A2[q];
                float muh2 = A1[q] + delta * wt;
                float sigc2 = T1[q];
                float sighc2 = A3[q] + dca * wt - muh2 * muc2;
                float sigh2 = muh2 - muh2 * muh2;
                float xv2 = fmaxf(sigh2 * sigc2, 0.f) + EPS_F;
                float sq2 = xv2 * rsqrtf(xv2);
                float n2 = (2.f * muh2 * muc2 + C1_F) * (2.f * sq2 + C2_F) * (2.f * sighc2 + C2_F);
                float d2 = (muh2 * muh2 + muc2 * muc2 + C1_F) * (sigh2 + sigc2 + C2_F) * (sq2 + C2_F + EPS_F);
                float dmh2 = muh2 - muc2;
                float Un = T2[q] * __fdividef(n2, d2) - dmh2 * dmh2;
                dacc += Un - T3[q];
            }
        }
    }
#pragma unroll
    for (int o = 16; o; o >>= 1) dacc += __shfl_xor_sync(0xffffffffu, dacc, o);
    if (lane == 0) {
        red[wid] = dacc;
        if (half == 0) Pi[wid >> 1] = pii;
    }
    __syncthreads();

    if (tid < 16) {
        float cs = (red[2 * tid] + red[2 * tid + 1]) * Pi[tid];
#pragma unroll
        for (int o = 8; o; o >>= 1) cs += __shfl_down_sync(0xffffu, cs, o);
        if (tid == 0) {
            g_part[i] = cs;
            __threadfence();
            int t = atomicAdd(&g_done, 1);
            red[0] = (t == 127) ? 1.f : 0.f;
        }
    }
    __syncthreads();

    if (red[0] != 0.f) {
        // last-done block: deterministic final reduction over 128 partials
        __threadfence();
        if (tid < 128) {
            float v = g_part[tid];
#pragma unroll
            for (int o = 16; o; o >>= 1) v += __shfl_xor_sync(0xffffffffu, v, o);
            if ((tid & 31) == 0) Pi[tid >> 5] = v;  // reuse Pi as 4-slot scratch
        }
        __syncthreads();
        if (tid == 0) {
            float A = Pi[0] + Pi[1] + Pi[2] + Pi[3];
            out[0] = -(g_S[0] + g_S[1] + A * (1.0f / 1024.0f)) * (1.0f / 2048.0f);
            g_done = 0;   // reset for next graph replay
        }
    }
}

extern "C" void kernel_launch(void* const* d_in, const int* in_sizes, int n_in,
                              void* d_out, int out_size) {
    const float* prob = (const float*)d_in[0];
    const float* c = (const float*)d_in[1];
    // d_in[2] (z) is unused by the reference.
    float* out = (float*)d_out;
    k_all<<<128, 1024>>>(prob, c, out);
}

// round 6
// speedup vs baseline: 1.3560x; 1.0052x over previous
#include <cuda_runtime.h>
#include <cstdint>

// HalftoneMARLLoss — banded redundant-base fused kernel (round 6).
// 128 independent blocks; block i handles image b=i>>6, row y0=(i&63)>>1,
// half xh=i&1 (16 candidates). Base maps computed only on the dependency
// band of row y0 (11-row SSIM band <- 21-row h-channels <- 31-row c channel),
// with all phases flat-index load-balanced across the 1024 threads.
// S_b is distributed: xh==0 blocks contribute their row-y0 Tb sum to the
// final reduction. Math identical to validated rounds 1/4/5 (rel_err ~2e-6).

#define HW 1024
#define WS_F 0.06f
#define C1_F 1e-4f
#define C2_F 9e-4f
#define EPS_F 1e-12f

#define GSUM 4.9859044930311974
#define GW0 ((float)(0.0439369336234074 / GSUM))
#define GW1 ((float)(0.1353352832366127 / GSUM))
#define GW2 ((float)(0.3246524673583497 / GSUM))
#define GW3 ((float)(0.6065306597126334 / GSUM))
#define GW4 ((float)(0.8824969025845955 / GSUM))
#define GW5 ((float)(1.0 / GSUM))
#define GW_TABLE {GW0, GW1, GW2, GW3, GW4, GW5, GW4, GW3, GW2, GW1, GW0}

__constant__ float GWC[11] = GW_TABLE;

__device__ float g_part[128];
__device__ int g_done;   // zero-init; reset by last block each launch

// ---- shared scratch layout (single array, float offsets) ----
// x-padded input tiles (width 42, valid cols 5..36):
#define OF_C31  0        // c,        31 rows (yy = y0-15+ry)
#define OF_H21  1302     // h,        21 rows (yy = y0-10+r)
#define OF_HC21 2184     // h*c
#define OF_C2   3066     // c*c
#define OF_D21  3948     // (c-muc)^2
// h-pass outputs (width 32):
#define OF_TC   4830     // 31 rows
#define OF_TH   5822     // 21 rows
#define OF_THC  6494
#define OF_TC2  7166
#define OF_TD   7838
// v-pass outputs:
#define OF_MUC  8510     // muc, 21 rows (yy = y0-10+r)
#define OF_MMUH 9182     // 11-row SSIM band (yy = y0-5+r)
#define OF_MHC  9534     // conv(h*c)
#define OF_MSIG 9886     // c2v, later sigc
#define OF_MWSC 10238
#define OF_MU0  10590
#define SM_FLOATS 10942

__device__ __forceinline__ void tf_round(uint32_t& x0, uint32_t& x1, int r) {
    x0 += x1;
    x1 = (x1 << r) | (x1 >> (32 - r));
    x1 ^= x0;
}

__device__ __forceinline__ float jax_uniform_elem(int e) {
    // JAX threefry2x32, key(42)=(0,42), partitionable: bits = x0^x1 of TF(0,e)
    const uint32_t k0 = 0u, k1 = 42u, ks2 = k0 ^ k1 ^ 0x1BD11BDAu;
    uint32_t x0 = 0u, x1 = (uint32_t)e;
    x0 += k0; x1 += k1;
    tf_round(x0, x1, 13); tf_round(x0, x1, 15); tf_round(x0, x1, 26); tf_round(x0, x1, 6);
    x0 += k1; x1 += ks2 + 1u;
    tf_round(x0, x1, 17); tf_round(x0, x1, 29); tf_round(x0, x1, 16); tf_round(x0, x1, 24);
    x0 += ks2; x1 += k0 + 2u;
    tf_round(x0, x1, 13); tf_round(x0, x1, 15); tf_round(x0, x1, 26); tf_round(x0, x1, 6);
    x0 += k0; x1 += k1 + 3u;
    tf_round(x0, x1, 17); tf_round(x0, x1, 29); tf_round(x0, x1, 16); tf_round(x0, x1, 24);
    x0 += k1; x1 += ks2 + 4u;
    tf_round(x0, x1, 13); tf_round(x0, x1, 15); tf_round(x0, x1, 26); tf_round(x0, x1, 6);
    x0 += ks2; x1 += k0 + 5u;
    uint32_t bits = x0 ^ x1;
    float f = __uint_as_float((bits >> 9) | 0x3f800000u) - 1.0f;
    return fmaxf(f, 0.0f);
}

__global__ __launch_bounds__(1024) void k_all(const float* __restrict__ prob,
                                              const float* __restrict__ cin,
                                              float* __restrict__ out) {
    __shared__ float S[SM_FLOATS];
    __shared__ float Wsh[121];
    __shared__ float Hrow[32], red[32], Pi[16], Sr[1];

    const float GW_[11] = GW_TABLE;   // static indices only -> immediates

    const int i = blockIdx.x;
    const int tid = threadIdx.x;
    const int b = i >> 6;
    const int hr = i & 63;
    const int y0 = hr >> 1;
    const int xh = hr & 1;
    const int bb = b * HW;
    const int ybase = y0 - 15;

    // ---- zero input tiles (covers x-pads and out-of-image rows) ----
    if (tid == 0) Sr[0] = 0.f;
#pragma unroll
    for (int u = tid; u < 4830; u += 1024) S[u] = 0.f;
    __syncthreads();

    // ---- phase 0: c loads (31 rows) + h RNG (21 rows) + Wsh (flat) ----
    for (int u = tid; u < 1785; u += 1024) {
        if (u < 992) {
            int ry = u >> 5, x = u & 31;
            int yy = ybase + ry;
            if ((unsigned)yy < 32u)
                S[OF_C31 + ry * 42 + x + 5] = cin[bb + yy * 32 + x];
        } else if (u < 1664) {
            int v = u - 992;
            int r = v >> 5, x = v & 31;
            int yy = y0 - 10 + r;
            if ((unsigned)yy < 32u) {
                int e = bb + yy * 32 + x;
                float cv = cin[e];
                float hv = (jax_uniform_elem(e) < prob[e]) ? 1.f : 0.f;
                S[OF_H21 + r * 42 + x + 5] = hv;
                S[OF_HC21 + r * 42 + x + 5] = hv * cv;
                S[OF_C2 + r * 42 + x + 5] = cv * cv;
                if (r == 10) Hrow[x] = hv;   // row y0
            }
        } else {
            int t = u - 1664;
            Wsh[t] = GWC[t / 11] * GWC[t % 11];
        }
    }
    __syncthreads();

    // ---- phase 1: horizontal passes (94 row-units, flat-balanced) ----
    for (int v = tid; v < 3008; v += 1024) {
        int unit = v >> 5, x = v & 31;
        const float* src;
        float* dst;
        if (unit < 31)      { src = &S[OF_C31  + unit * 42 + x];        dst = &S[OF_TC  + unit * 32 + x]; }
        else if (unit < 52) { src = &S[OF_H21  + (unit - 31) * 42 + x]; dst = &S[OF_TH  + (unit - 31) * 32 + x]; }
        else if (unit < 73) { src = &S[OF_HC21 + (unit - 52) * 42 + x]; dst = &S[OF_THC + (unit - 52) * 32 + x]; }
        else                { src = &S[OF_C2   + (unit - 73) * 42 + x]; dst = &S[OF_TC2 + (unit - 73) * 32 + x]; }
        float s = 0.f;
#pragma unroll
        for (int j = 0; j < 11; j++) s += GW_[j] * src[j];
        *dst = s;
    }
    __syncthreads();

    // ---- phase 2: vertical passes (54 row-units: 21 muc + 3x11 band) ----
    for (int v = tid; v < 1728; v += 1024) {
        int unit = v >> 5, x = v & 31;
        const float* src;
        float* dst;
        if (unit < 21)      { src = &S[OF_TC  + unit * 32 + x];        dst = &S[OF_MUC  + unit * 32 + x]; }
        else if (unit < 32) { src = &S[OF_TH  + (unit - 21) * 32 + x]; dst = &S[OF_MMUH + (unit - 21) * 32 + x]; }
        else if (unit < 43) { src = &S[OF_THC + (unit - 32) * 32 + x]; dst = &S[OF_MHC  + (unit - 32) * 32 + x]; }
        else                { src = &S[OF_TC2 + (unit - 43) * 32 + x]; dst = &S[OF_MSIG + (unit - 43) * 32 + x]; }
        float s = 0.f;
#pragma unroll
        for (int j = 0; j < 11; j++) s += GW_[j] * src[j * 32];
        *dst = s;
    }
    __syncthreads();

    // ---- phase 3a: dcm = (c - muc)^2 on 21 rows (in-image only) ----
    if (tid < 672) {
        int r = tid >> 5, x = tid & 31;
        int yy = y0 - 10 + r;
        if ((unsigned)yy < 32u) {
            float d = S[OF_C31 + (r + 5) * 42 + x + 5] - S[OF_MUC + r * 32 + x];
            S[OF_D21 + r * 42 + x + 5] = d * d;
        }
    }
    __syncthreads();

    // ---- phase 3b: dcm horizontal pass (21 rows) ----
    if (tid < 672) {
        int r = tid >> 5, x = tid & 31;
        const float* src = &S[OF_D21 + r * 42 + x];
        float s = 0.f;
#pragma unroll
        for (int j = 0; j < 11; j++) s += GW_[j] * src[j];
        S[OF_TD + r * 32 + x] = s;
    }
    __syncthreads();

    // ---- phase 4: cvar v-pass + per-pixel base reward on 11-row band ----
    if (tid < 352) {
        int r = tid >> 5, x = tid & 31;
        const float* src = &S[OF_TD + r * 32 + x];
        float cvar = 0.f;
#pragma unroll
        for (int j = 0; j < 11; j++) cvar += GW_[j] * src[j * 32];

        int q = r * 32 + x;
        float muh = S[OF_MMUH + q];
        float muc = S[OF_MUC + (r + 5) * 32 + x];
        float hcv = S[OF_MHC + q];
        float c2v = S[OF_MSIG + q];

        float sigc = c2v - muc * muc;
        float sigh = muh - muh * muh;          // conv(h^2)==conv(h), h binary
        float sighc = hcv - muh * muc;
        float xv = fmaxf(sigh * sigc, 0.f) + EPS_F;
        float sq = xv * rsqrtf(xv);
        float num = (2.f * muh * muc + C1_F) * (2.f * sq + C2_F) * (2.f * sighc + C2_F);
        float den = (muh * muh + muc * muc + C1_F) * (sigh + sigc + C2_F) * (sq + C2_F + EPS_F);
        float ssim = __fdividef(num, den);
        float cc2 = cvar + EPS_F;
        float ccon = fminf(2.f * (cc2 * rsqrtf(cc2)), 1.f);
        float wsc = WS_F * ccon;
        float dmh = muh - muc;
        float U0 = wsc * ssim - dmh * dmh;

        S[OF_MSIG + q] = sigc;
        S[OF_MWSC + q] = wsc;
        S[OF_MU0 + q] = U0;

        // distributed S_b: xh==0 block sums Tb over its own row y0 (r==5)
        if (xh == 0 && r == 5) {
            float Tb = U0 + WS_F - wsc;
#pragma unroll
            for (int o = 16; o; o >>= 1) Tb += __shfl_xor_sync(0xffffffffu, Tb, o);
            if (x == 0) Sr[0] = Tb;
        }
    }
    __syncthreads();

    // ---- flip phase: 16 candidates, 2 warps each ----
    const int wid = tid >> 5;
    const int lane = tid & 31;
    const int cand = xh * 16 + (wid >> 1);
    const int half = wid & 1;

    const int aidx = bb + y0 * 32 + cand;
    float hA = Hrow[cand];
    float delta = 1.f - 2.f * hA;
    float pa = prob[aidx];
    float pii = (hA == 0.f) ? pa : (1.f - pa);
    float dca = delta * cin[aidx];

    float dacc = 0.f;
#pragma unroll
    for (int k = 0; k < 2; k++) {
        int t = half * 64 + k * 32 + lane;
        if (t < 121) {
            int r = t / 11;
            int cidx = t - r * 11;
            int yy = y0 + r - 5;
            int xx = cand + cidx - 5;
            if (((unsigned)yy < 32u) & ((unsigned)xx < 32u)) {
                float wt = Wsh[t];
                int q = r * 32 + xx;               // band row r == window row
                float muc2 = S[OF_MUC + (r + 5) * 32 + xx];
                float muh2 = S[OF_MMUH + q] + delta * wt;
                float sigc2 = S[OF_MSIG + q];
                float sighc2 = S[OF_MHC + q] + dca * wt - muh2 * muc2;
                float sigh2 = muh2 - muh2 * muh2;
                float xv2 = fmaxf(sigh2 * sigc2, 0.f) + EPS_F;
                float sq2 = xv2 * rsqrtf(xv2);
                float n2 = (2.f * muh2 * muc2 + C1_F) * (2.f * sq2 + C2_F) * (2.f * sighc2 + C2_F);
                float d2 = (muh2 * muh2 + muc2 * muc2 + C1_F) * (sigh2 + sigc2 + C2_F) * (sq2 + C2_F + EPS_F);
                float dmh2 = muh2 - muc2;
                float Un = S[OF_MWSC + q] * __fdividef(n2, d2) - dmh2 * dmh2;
                dacc += Un - S[OF_MU0 + q];
            }
        }
    }
#pragma unroll
    for (int o = 16; o; o >>= 1) dacc += __shfl_xor_sync(0xffffffffu, dacc, o);
    if (lane == 0) {
        red[wid] = dacc;
        if (half == 0) Pi[wid >> 1] = pii;
    }
    __syncthreads();

    if (tid < 16) {
        float cs = (red[2 * tid] + red[2 * tid + 1]) * Pi[tid];
#pragma unroll
        for (int o = 8; o; o >>= 1) cs += __shfl_down_sync(0xffffu, cs, o);
        if (tid == 0) {
            g_part[i] = Sr[0] + cs * (1.0f / 1024.0f);
            __threadfence();
            int t = atomicAdd(&g_done, 1);
            red[0] = (t == 127) ? 1.f : 0.f;
        }
    }
    __syncthreads();

    if (red[0] != 0.f) {
        // last-done block: deterministic final reduction over 128 partials
        __threadfence();
        if (tid < 128) {
            float v = g_part[tid];
#pragma unroll
            for (int o = 16; o; o >>= 1) v += __shfl_xor_sync(0xffffffffu, v, o);
            if ((tid & 31) == 0) Pi[tid >> 5] = v;
        }
        __syncthreads();
        if (tid == 0) {
            float A = Pi[0] + Pi[1] + Pi[2] + Pi[3];
            out[0] = -A * (1.0f / 2048.0f);
            g_done = 0;   // reset for next graph replay
        }
    }
}

extern "C" void kernel_launch(void* const* d_in, const int* in_sizes, int n_in,
                              void* d_out, int out_size) {
    const float* prob = (const float*)d_in[0];
    const float* c = (const float*)d_in[1];
    // d_in[2] (z) is unused by the reference.
    float* out = (float*)d_out;
    k_all<<<128, 1024>>>(prob, c, out);
}

// round 8
// speedup vs baseline: 1.5841x; 1.1682x over previous
#include <cuda_runtime.h>
#include <cstdint>

// HalftoneMARLLoss — banded fused kernel, round 8.
// Round 7 structure (uniform indexing, merged phases, 7 barriers, LDG-free
// flip phase) + fix: P3 restores the row-validity guard that round 6 had —
// out-of-image rows must contribute ZERO to the cvar conv (SAME padding);
// without the guard (c=0, muc!=0) leaks muc^2 into border cvar (rel_err 4e-3).
// 128 independent blocks; block i: image b=i>>6, row y0=(i&63)>>1, half xh=i&1.

#define HW 1024
#define WS_F 0.06f
#define C1_F 1e-4f
#define C2_F 9e-4f
#define EPS_F 1e-12f

#define GSUM 4.9859044930311974
#define GW0 ((float)(0.0439369336234074 / GSUM))
#define GW1 ((float)(0.1353352832366127 / GSUM))
#define GW2 ((float)(0.3246524673583497 / GSUM))
#define GW3 ((float)(0.6065306597126334 / GSUM))
#define GW4 ((float)(0.8824969025845955 / GSUM))
#define GW5 ((float)(1.0 / GSUM))
#define GW_TABLE {GW0, GW1, GW2, GW3, GW4, GW5, GW4, GW3, GW2, GW1, GW0}

__constant__ float GWC[11] = GW_TABLE;

__device__ float g_part[128];
__device__ int g_done;   // zero-init; reset by last block each launch

// ---- shared layout: all padded tiles contiguous (94 rows x 42), then all
// dense h-pass outputs contiguous (94 rows x 32), then v-pass maps. ----
#define OF_C31  0        // c,   31 padded rows (ry: yy = y0-15+ry)
#define OF_H21  1302     // h,   21 rows (r: yy = y0-10+r)   [global rows 31..51]
#define OF_HC21 2184     //                                   [rows 52..72]
#define OF_C2   3066     //                                   [rows 73..93]
#define OF_TC   3948     // dense h-pass outputs, 94 rows x 32 (same row order)
#define OF_MUC  6956     // v-pass: muc 21 rows
#define OF_MMUH 7628     // 11-row band (yy = y0-5+r)
#define OF_MHC  7980
#define OF_MSIG 8332     // c2v, overwritten with sigc in P4
#define OF_MWSC 8684
#define OF_MU0  9036
#define OF_TD   9388     // dcm^2 h-pass, 21 rows x 32
#define SM_FLOATS 10060

__device__ __forceinline__ void tf_round(uint32_t& x0, uint32_t& x1, int r) {
    x0 += x1;
    x1 = (x1 << r) | (x1 >> (32 - r));
    x1 ^= x0;
}

__device__ __forceinline__ float jax_uniform_elem(int e) {
    // JAX threefry2x32, key(42)=(0,42), partitionable: bits = x0^x1 of TF(0,e)
    const uint32_t k0 = 0u, k1 = 42u, ks2 = k0 ^ k1 ^ 0x1BD11BDAu;
    uint32_t x0 = 0u, x1 = (uint32_t)e;
    x0 += k0; x1 += k1;
    tf_round(x0, x1, 13); tf_round(x0, x1, 15); tf_round(x0, x1, 26); tf_round(x0, x1, 6);
    x0 += k1; x1 += ks2 + 1u;
    tf_round(x0, x1, 17); tf_round(x0, x1, 29); tf_round(x0, x1, 16); tf_round(x0, x1, 24);
    x0 += ks2; x1 += k0 + 2u;
    tf_round(x0, x1, 13); tf_round(x0, x1, 15); tf_round(x0, x1, 26); tf_round(x0, x1, 6);
    x0 += k0; x1 += k1 + 3u;
    tf_round(x0, x1, 17); tf_round(x0, x1, 29); tf_round(x0, x1, 16); tf_round(x0, x1, 24);
    x0 += k1; x1 += ks2 + 4u;
    tf_round(x0, x1, 13); tf_round(x0, x1, 15); tf_round(x0, x1, 26); tf_round(x0, x1, 6);
    x0 += ks2; x1 += k0 + 5u;
    uint32_t bits = x0 ^ x1;
    float f = __uint_as_float((bits >> 9) | 0x3f800000u) - 1.0f;
    return fmaxf(f, 0.0f);
}

__global__ __launch_bounds__(1024) void k_all(const float* __restrict__ prob,
                                              const float* __restrict__ cin,
                                              float* __restrict__ out) {
    __shared__ float S[SM_FLOATS];
    __shared__ float Wsh[121];
    __shared__ float Hrow[32], Prow[32], red[32], Pi[16], Sr[1];

    const float GW_[11] = GW_TABLE;   // static indices only -> immediates

    const int i = blockIdx.x;
    const int tid = threadIdx.x;
    const int b = i >> 6;
    const int hr = i & 63;
    const int y0 = hr >> 1;
    const int xh = hr & 1;
    const int bb = b * HW;

    // ================= P0: pads + loads + RNG + Wsh (one item each) ========
    if (tid == 0) Sr[0] = 0.f;
    if (tid < 940) {                       // zero the 10 pad cols of 94 rows
        int row = tid / 10, cc = tid - row * 10;
        int col = (cc < 5) ? cc : cc + 32;
        S[row * 42 + col] = 0.f;
    }
    if (tid >= 903) {                      // Gaussian outer-product table
        int t = tid - 903;
        Wsh[t] = GWC[t / 11] * GWC[t % 11];
    }
    if (tid < 992) {                       // c rows (31) + RNG rows (21)
        int ry = tid >> 5, x = tid & 31;
        int yy = y0 - 15 + ry;
        bool valid = (unsigned)yy < 32u;
        int e = bb + yy * 32 + x;
        float cv = valid ? cin[e] : 0.f;   // invalid rows store 0 (self-zeroing)
        S[OF_C31 + ry * 42 + x + 5] = cv;
        int r = ry - 5;
        if ((unsigned)r < 21u) {
            float hv = 0.f, pv = 0.f;
            if (valid) {
                pv = prob[e];
                hv = (jax_uniform_elem(e) < pv) ? 1.f : 0.f;
            }
            S[OF_H21 + r * 42 + x + 5] = hv;
            S[OF_HC21 + r * 42 + x + 5] = hv * cv;
            S[OF_C2 + r * 42 + x + 5] = cv * cv;
            if (r == 10) { Hrow[x] = hv; Prow[x] = pv; }
        }
    }
    __syncthreads();

    // ================= P1: horizontal passes, 94 uniform units =============
    for (int v = tid; v < 3008; v += 1024) {
        int unit = v >> 5, x = v & 31;
        const float* src = &S[unit * 42 + x];
        float s = 0.f;
#pragma unroll
        for (int j = 0; j < 11; j++) s += GW_[j] * src[j];
        S[OF_TC + unit * 32 + x] = s;
    }
    __syncthreads();

    // ================= P2: vertical passes, 54 units =======================
    for (int v = tid; v < 1728; v += 1024) {
        int unit = v >> 5, x = v & 31;
        int adj = ((unit >= 21) ? 10 : 0) + ((unit >= 32) ? 10 : 0) + ((unit >= 43) ? 10 : 0);
        const float* src = &S[OF_TC + (unit + adj) * 32 + x];
        float s = 0.f;
#pragma unroll
        for (int j = 0; j < 11; j++) s += GW_[j] * src[j * 32];
        S[OF_MUC + unit * 32 + x] = s;
    }
    __syncthreads();

    // ================= P3: fused dcm^2 + horizontal pass (21 rows) =========
    // ROW-VALIDITY GUARD: out-of-image rows must store 0 (SAME zero padding) —
    // c is 0 there but muc is not, so (c-muc)^2 would leak into border cvar.
    if (tid < 672) {
        int r = tid >> 5, x = tid & 31;
        int yy = y0 - 10 + r;
        float s = 0.f;
        if ((unsigned)yy < 32u) {
            const float* crow = &S[OF_C31 + (r + 5) * 42 + 5];  // index by xx
            const float* mrow = &S[OF_MUC + r * 32];
#pragma unroll
            for (int j = 0; j < 11; j++) {
                int xx = x + j - 5;
                if ((unsigned)xx < 32u) {
                    float d = crow[xx] - mrow[xx];
                    s += GW_[j] * (d * d);
                }
            }
        }
        S[OF_TD + r * 32 + x] = s;
    }
    __syncthreads();

    // ================= P4: cvar v-pass + base reward (11-row band) =========
    if (tid < 352) {
        int r = tid >> 5, x = tid & 31;
        const float* src = &S[OF_TD + r * 32 + x];
        float cvar = 0.f;
#pragma unroll
        for (int j = 0; j < 11; j++) cvar += GW_[j] * src[j * 32];

        int q = r * 32 + x;
        float muh = S[OF_MMUH + q];
        float muc = S[OF_MUC + (r + 5) * 32 + x];
        float hcv = S[OF_MHC + q];
        float c2v = S[OF_MSIG + q];

        float sigc = c2v - muc * muc;
        float sigh = muh - muh * muh;          // conv(h^2)==conv(h), h binary
        float sighc = hcv - muh * muc;
        float xv = fmaxf(sigh * sigc, 0.f) + EPS_F;
        float sq = xv * rsqrtf(xv);
        float num = (2.f * muh * muc + C1_F) * (2.f * sq + C2_F) * (2.f * sighc + C2_F);
        float den = (muh * muh + muc * muc + C1_F) * (sigh + sigc + C2_F) * (sq + C2_F + EPS_F);
        float ssim = __fdividef(num, den);
        float cc2 = cvar + EPS_F;
        float ccon = fminf(2.f * (cc2 * rsqrtf(cc2)), 1.f);
        float wsc = WS_F * ccon;
        float dmh = muh - muc;
        float U0 = wsc * ssim - dmh * dmh;

        S[OF_MSIG + q] = sigc;
        S[OF_MWSC + q] = wsc;
        S[OF_MU0 + q] = U0;

        // distributed S_b: xh==0 block sums Tb over its own row y0 (r==5)
        if (xh == 0 && r == 5) {
            float Tb = U0 + WS_F - wsc;
#pragma unroll
            for (int o = 16; o; o >>= 1) Tb += __shfl_xor_sync(0xffffffffu, Tb, o);
            if (x == 0) Sr[0] = Tb;
        }
    }
    __syncthreads();

    // ================= P5: flip phase, 16 candidates x 2 warps =============
    const int wid = tid >> 5;
    const int lane = tid & 31;
    const int cand = xh * 16 + (wid >> 1);
    const int half = wid & 1;

    float hA = Hrow[cand];
    float delta = 1.f - 2.f * hA;
    float pa = Prow[cand];
    float pii = (hA == 0.f) ? pa : (1.f - pa);
    float dca = delta * S[OF_C31 + 15 * 42 + 5 + cand];   // c at (y0, cand)

    float dacc = 0.f;
#pragma unroll
    for (int k = 0; k < 2; k++) {
        int t = half * 64 + k * 32 + lane;
        if (t < 121) {
            int r = t / 11;
            int cidx = t - r * 11;
            int yy = y0 + r - 5;
            int xx = cand + cidx - 5;
            if (((unsigned)yy < 32u) & ((unsigned)xx < 32u)) {
                float wt = Wsh[t];
                int q = r * 32 + xx;
                float muc2 = S[OF_MUC + (r + 5) * 32 + xx];
                float muh2 = S[OF_MMUH + q] + delta * wt;
                float sigc2 = S[OF_MSIG + q];
                float sighc2 = S[OF_MHC + q] + dca * wt - muh2 * muc2;
                float sigh2 = muh2 - muh2 * muh2;
                float xv2 = fmaxf(sigh2 * sigc2, 0.f) + EPS_F;
                float sq2 = xv2 * rsqrtf(xv2);
                float n2 = (2.f * muh2 * muc2 + C1_F) * (2.f * sq2 + C2_F) * (2.f * sighc2 + C2_F);
                float d2 = (muh2 * muh2 + muc2 * muc2 + C1_F) * (sigh2 + sigc2 + C2_F) * (sq2 + C2_F + EPS_F);
                float dmh2 = muh2 - muc2;
                float Un = S[OF_MWSC + q] * __fdividef(n2, d2) - dmh2 * dmh2;
                dacc += Un - S[OF_MU0 + q];
            }
        }
    }
#pragma unroll
    for (int o = 16; o; o >>= 1) dacc += __shfl_xor_sync(0xffffffffu, dacc, o);
    if (lane == 0) {
        red[wid] = dacc;
        if (half == 0) Pi[wid >> 1] = pii;
    }
    __syncthreads();

    // ================= P6: block combine + last-block final reduce =========
    if (tid < 16) {
        float cs = (red[2 * tid] + red[2 * tid + 1]) * Pi[tid];
#pragma unroll
        for (int o = 8; o; o >>= 1) cs += __shfl_down_sync(0xffffu, cs, o);
        if (tid == 0) {
            g_part[i] = Sr[0] + cs * (1.0f / 1024.0f);
            __threadfence();
            int t = atomicAdd(&g_done, 1);
            red[0] = (t == 127) ? 1.f : 0.f;
        }
    }
    __syncthreads();

    if (red[0] != 0.f) {
        __threadfence();
        if (tid < 128) {
            float v = g_part[tid];
#pragma unroll
            for (int o = 16; o; o >>= 1) v += __shfl_xor_sync(0xffffffffu, v, o);
            if ((tid & 31) == 0) Pi[tid >> 5] = v;
        }
        __syncthreads();
        if (tid == 0) {
            float A = Pi[0] + Pi[1] + Pi[2] + Pi[3];
            out[0] = -A * (1.0f / 2048.0f);
            g_done = 0;   // reset for next graph replay
        }
    }
}

extern "C" void kernel_launch(void* const* d_in, const int* in_sizes, int n_in,
                              void* d_out, int out_size) {
    const float* prob = (const float*)d_in[0];
    const float* c = (const float*)d_in[1];
    // d_in[2] (z) is unused by the reference.
    float* out = (float*)d_out;
    k_all<<<128, 1024>>>(prob, c, out);
}

// round 9
// speedup vs baseline: 1.6087x; 1.0155x over previous
#include <cuda_runtime.h>
#include <cstdint>

// HalftoneMARLLoss — round 9: RNG/conv warp-overlap + vectorized convs.
// 128 independent blocks; block i: image b=i>>6, row y0=(i&63)>>1, half xh=i&1.
// Padded tiles width 44 (16B-aligned rows) -> float4 h-pass quads, float2/4
// v-pass. P0b runs threefry (warps 0-20) CONCURRENTLY with the c h-pass
// (warps 21-31). Math identical to validated round 8 (rel_err 2e-6).

#define HW 1024
#define WS_F 0.06f
#define C1_F 1e-4f
#define C2_F 9e-4f
#define EPS_F 1e-12f

#define GSUM 4.9859044930311974
#define GW0 ((float)(0.0439369336234074 / GSUM))
#define GW1 ((float)(0.1353352832366127 / GSUM))
#define GW2 ((float)(0.3246524673583497 / GSUM))
#define GW3 ((float)(0.6065306597126334 / GSUM))
#define GW4 ((float)(0.8824969025845955 / GSUM))
#define GW5 ((float)(1.0 / GSUM))
#define GW_TABLE {GW0, GW1, GW2, GW3, GW4, GW5, GW4, GW3, GW2, GW1, GW0}

__constant__ float GWC[11] = GW_TABLE;

__device__ float g_part[128];
__device__ int g_done;   // zero-init; reset by last block each launch

// ---- shared layout (floats). Padded tiles: width 44, interior cols 5..36. ----
// padded rows 0..93: c rows 0..30 (ry: yy=y0-15+ry), h rows 31..51 (r: yy=y0-10+r),
// hc rows 52..72, c2 rows 73..93.
#define PW 44
#define OF_H21  (31 * PW)     // 1364
#define OF_HC21 (52 * PW)     // 2288
#define OF_C2   (73 * PW)     // 3212
#define OF_TC   4136          // dense h-pass outputs, 94 rows x 32 (same order)
#define OF_MUC  7144          // muc padded, 21 rows x 44 (yy = y0-10+r)
#define MAPS    8096          // 55 rows x 32: muh[0..10],hc[11..21],sigc[22..32],wsc[33..43],U0[44..54]
#define OF_TD   9856          // dcm^2 h-pass, 21 rows x 32
#define SM_FLOATS 10528

__device__ __forceinline__ void tf_round(uint32_t& x0, uint32_t& x1, int r) {
    x0 += x1;
    x1 = (x1 << r) | (x1 >> (32 - r));
    x1 ^= x0;
}

__device__ __forceinline__ float jax_uniform_elem(int e) {
    // JAX threefry2x32, key(42)=(0,42), partitionable: bits = x0^x1 of TF(0,e)
    const uint32_t k0 = 0u, k1 = 42u, ks2 = k0 ^ k1 ^ 0x1BD11BDAu;
    uint32_t x0 = 0u, x1 = (uint32_t)e;
    x0 += k0; x1 += k1;
    tf_round(x0, x1, 13); tf_round(x0, x1, 15); tf_round(x0, x1, 26); tf_round(x0, x1, 6);
    x0 += k1; x1 += ks2 + 1u;
    tf_round(x0, x1, 17); tf_round(x0, x1, 29); tf_round(x0, x1, 16); tf_round(x0, x1, 24);
    x0 += ks2; x1 += k0 + 2u;
    tf_round(x0, x1, 13); tf_round(x0, x1, 15); tf_round(x0, x1, 26); tf_round(x0, x1, 6);
    x0 += k0; x1 += k1 + 3u;
    tf_round(x0, x1, 17); tf_round(x0, x1, 29); tf_round(x0, x1, 16); tf_round(x0, x1, 24);
    x0 += k1; x1 += ks2 + 4u;
    tf_round(x0, x1, 13); tf_round(x0, x1, 15); tf_round(x0, x1, 26); tf_round(x0, x1, 6);
    x0 += ks2; x1 += k0 + 5u;
    uint32_t bits = x0 ^ x1;
    float f = __uint_as_float((bits >> 9) | 0x3f800000u) - 1.0f;
    return fmaxf(f, 0.0f);
}

__global__ __launch_bounds__(1024) void k_all(const float* __restrict__ prob,
                                              const float* __restrict__ cin,
                                              float* __restrict__ out) {
    __shared__ __align__(16) float S[SM_FLOATS];
    __shared__ float Wsh[121];
    __shared__ float Hrow[32], Prow[32], red[32], Pi[16], Sr[1];

    const float GW_[11] = GW_TABLE;   // static indices only -> immediates

    const int i = blockIdx.x;
    const int tid = threadIdx.x;
    const int b = i >> 6;
    const int hr = i & 63;
    const int y0 = hr >> 1;
    const int xh = hr & 1;
    const int bb = b * HW;

    // ================= P0a: pads + c loads + prob preload + Wsh ============
    if (tid == 0) Sr[0] = 0.f;
    {   // main pads: 94 rows x 12 cols (0..4 and 37..43) = 1128 cells
        int row = tid / 12, cc = tid - row * 12;
        if (row < 94) S[row * PW + (cc < 5 ? cc : cc + 32)] = 0.f;
        int m = tid + 1024;
        if (m < 1128) {
            int r2 = m / 12, c2 = m - r2 * 12;
            S[r2 * PW + (c2 < 5 ? c2 : c2 + 32)] = 0.f;
        }
        if (tid < 252) {   // muc pads: 21 x 12
            int r3 = tid / 12, c3 = tid - r3 * 12;
            S[OF_MUC + r3 * PW + (c3 < 5 ? c3 : c3 + 32)] = 0.f;
        }
    }
    if (tid >= 903) { int t = tid - 903; Wsh[t] = GWC[t / 11] * GWC[t % 11]; }
    if (tid < 992) {   // c rows, yy = y0-15+ry; invalid rows store 0
        int ry = tid >> 5, x = tid & 31;
        int yy = y0 - 15 + ry;
        float cv = 0.f;
        if ((unsigned)yy < 32u) cv = cin[bb + yy * 32 + x];
        S[ry * PW + x + 5] = cv;
    }
    float pv = 0.f;    // prob preload for this thread's RNG element
    if (tid < 672) {
        int r = tid >> 5, x = tid & 31;
        int yy = y0 - 10 + r;
        if ((unsigned)yy < 32u) pv = prob[bb + yy * 32 + x];
        if (r == 10) Prow[x] = pv;
    }
    __syncthreads();

    // ================= P0b: RNG (warps 0-20)  ||  c h-pass (warps 21-31) ===
    if (tid < 672) {
        int r = tid >> 5, x = tid & 31;
        int yy = y0 - 10 + r;
        bool valid = (unsigned)yy < 32u;
        float u = jax_uniform_elem(bb + yy * 32 + x);   // garbage e if invalid: unused
        float hv = (valid && (u < pv)) ? 1.f : 0.f;
        float cv = S[(r + 5) * PW + x + 5];             // c at same pixel (0 if invalid)
        S[OF_H21 + r * PW + x + 5] = hv;
        S[OF_HC21 + r * PW + x + 5] = hv * cv;
        S[OF_C2 + r * PW + x + 5] = cv * cv;
        if (r == 10) Hrow[x] = hv;
    } else {
        int t = tid - 672;   // 0..351, covering 992 scalar items (31 c rows)
#pragma unroll
        for (int k = 0; k < 3; k++) {
            int u = t + 352 * k;
            if (u < 992) {
                int unit = u >> 5, x = u & 31;
                const float* src = &S[unit * PW + x];
                float s = 0.f;
#pragma unroll
                for (int j = 0; j < 11; j++) s += GW_[j] * src[j];
                S[OF_TC + unit * 32 + x] = s;
            }
        }
    }
    __syncthreads();

    // ========== P1b: h-channel h-pass (63 rows, float4 quads) + muc v-pass ==
    if (tid < 504) {          // 63 rows x 8 quads
        int unit = tid >> 3, qx = (tid & 7) << 2;
        int row = 31 + unit;
        const float4* p4 = reinterpret_cast<const float4*>(&S[row * PW + qx]);
        float4 A = p4[0], B = p4[1], C4 = p4[2], D4 = p4[3];
        float v[16] = {A.x, A.y, A.z, A.w, B.x, B.y, B.z, B.w,
                       C4.x, C4.y, C4.z, C4.w, D4.x, D4.y, D4.z, D4.w};
        float o0 = 0.f, o1 = 0.f, o2 = 0.f, o3 = 0.f;
#pragma unroll
        for (int j = 0; j < 11; j++) {
            float w = GW_[j];
            o0 += w * v[j]; o1 += w * v[j + 1]; o2 += w * v[j + 2]; o3 += w * v[j + 3];
        }
        float4 o = {o0, o1, o2, o3};
        *reinterpret_cast<float4*>(&S[OF_TC + row * 32 + qx]) = o;
    } else if (tid < 840) {   // muc v-pass: 21 rows x 16 float2 pairs
        int p = tid - 504;
        int unit = p >> 4, px = (p & 15) << 1;
        float s0 = 0.f, s1 = 0.f;
#pragma unroll
        for (int j = 0; j < 11; j++) {
            float2 t2 = *reinterpret_cast<const float2*>(&S[OF_TC + (unit + j) * 32 + px]);
            s0 += GW_[j] * t2.x; s1 += GW_[j] * t2.y;
        }
        int yy = y0 - 10 + unit;
        if ((unsigned)yy >= 32u) { s0 = 0.f; s1 = 0.f; }   // invalid rows -> 0
        S[OF_MUC + unit * PW + 5 + px] = s0;               // odd col: scalar stores
        S[OF_MUC + unit * PW + 6 + px] = s1;
    }
    __syncthreads();

    // ========== P2: band v-pass (33 rows, quads) + dcm^2 h-pass (pairs) ====
    if (tid < 264) {          // 33 units x 8 quads
        int u = tid >> 3, qx = (tid & 7) << 2;
        int ch = u / 11;
        int r = u - ch * 11;
        int srow = 31 + ch * 21 + r;
        float a0 = 0.f, a1 = 0.f, a2 = 0.f, a3 = 0.f;
#pragma unroll
        for (int j = 0; j < 11; j++) {
            float4 t = *reinterpret_cast<const float4*>(&S[OF_TC + (srow + j) * 32 + qx]);
            float w = GW_[j];
            a0 += w * t.x; a1 += w * t.y; a2 += w * t.z; a3 += w * t.w;
        }
        float4 o = {a0, a1, a2, a3};
        *reinterpret_cast<float4*>(&S[MAPS + u * 32 + qx]) = o;
    } else if (tid < 600) {   // dcm^2 fused h-pass: 21 rows x 16 pairs
        int d = tid - 264;
        int r = d >> 4, px = (d & 15) << 1;
        float d2[12];
#pragma unroll
        for (int k = 0; k < 6; k++) {
            float2 cv2 = *reinterpret_cast<const float2*>(&S[(r + 5) * PW + px + 2 * k]);
            float2 mv2 = *reinterpret_cast<const float2*>(&S[OF_MUC + r * PW + px + 2 * k]);
            float dx = cv2.x - mv2.x, dy = cv2.y - mv2.y;
            d2[2 * k] = dx * dx; d2[2 * k + 1] = dy * dy;
        }
        float s0 = 0.f, s1 = 0.f;
#pragma unroll
        for (int j = 0; j < 11; j++) { s0 += GW_[j] * d2[j]; s1 += GW_[j] * d2[j + 1]; }
        float2 o = {s0, s1};
        *reinterpret_cast<float2*>(&S[OF_TD + r * 32 + px]) = o;
    }
    __syncthreads();

    // ================= P4: cvar v-pass + base reward (11-row band) =========
    if (tid < 352) {
        int r = tid >> 5, x = tid & 31;
        const float* src = &S[OF_TD + r * 32 + x];
        float cvar = 0.f;
#pragma unroll
        for (int j = 0; j < 11; j++) cvar += GW_[j] * src[j * 32];

        int q = r * 32 + x;
        float muh = S[MAPS + q];
        float hcv = S[MAPS + 352 + q];
        float c2v = S[MAPS + 704 + q];
        float muc = S[OF_MUC + (r + 5) * PW + 5 + x];

        float sigc = c2v - muc * muc;
        float sigh = muh - muh * muh;          // conv(h^2)==conv(h), h binary
        float sighc = hcv - muh * muc;
        float xv = fmaxf(sigh * sigc, 0.f) + EPS_F;
        float sq = xv * rsqrtf(xv);
        float num = (2.f * muh * muc + C1_F) * (2.f * sq + C2_F) * (2.f * sighc + C2_F);
        float den = (muh * muh + muc * muc + C1_F) * (sigh + sigc + C2_F) * (sq + C2_F + EPS_F);
        float ssim = __fdividef(num, den);
        float cc2 = cvar + EPS_F;
        float ccon = fminf(2.f * (cc2 * rsqrtf(cc2)), 1.f);
        float wsc = WS_F * ccon;
        float dmh = muh - muc;
        float U0 = wsc * ssim - dmh * dmh;

        S[MAPS + 704 + q] = sigc;   // overwrite c2v with sigc
        S[MAPS + 1056 + q] = wsc;
        S[MAPS + 1408 + q] = U0;

        // distributed S_b: xh==0 block sums Tb over its own row y0 (r==5)
        if (xh == 0 && r == 5) {
            float Tb = U0 + WS_F - wsc;
#pragma unroll
            for (int o = 16; o; o >>= 1) Tb += __shfl_xor_sync(0xffffffffu, Tb, o);
            if (x == 0) Sr[0] = Tb;
        }
    }
    __syncthreads();

    // ================= P5: flip phase, 16 candidates x 2 warps =============
    const int wid = tid >> 5;
    const int lane = tid & 31;
    const int cand = xh * 16 + (wid >> 1);
    const int half = wid & 1;

    float hA = Hrow[cand];
    float delta = 1.f - 2.f * hA;
    float pa = Prow[cand];
    float pii = (hA == 0.f) ? pa : (1.f - pa);
    float dca = delta * S[15 * PW + 5 + cand];   // c at (y0, cand)

    float dacc = 0.f;
#pragma unroll
    for (int k = 0; k < 2; k++) {
        int t = half * 64 + k * 32 + lane;
        if (t < 121) {
            int rb = t / 11;
            int cidx = t - rb * 11;
            int yy = y0 + rb - 5;
            int xx = cand + cidx - 5;
            if (((unsigned)yy < 32u) & ((unsigned)xx < 32u)) {
                float wt = Wsh[t];
                int q = rb * 32 + xx;
                float muc2 = S[OF_MUC + (rb + 5) * PW + 5 + xx];
                float muh2 = S[MAPS + q] + delta * wt;
                float sigc2 = S[MAPS + 704 + q];
                float sighc2 = S[MAPS + 352 + q] + dca * wt - muh2 * muc2;
                float sigh2 = muh2 - muh2 * muh2;
                float xv2 = fmaxf(sigh2 * sigc2, 0.f) + EPS_F;
                float sq2 = xv2 * rsqrtf(xv2);
                float n2 = (2.f * muh2 * muc2 + C1_F) * (2.f * sq2 + C2_F) * (2.f * sighc2 + C2_F);
                float d2v = (muh2 * muh2 + muc2 * muc2 + C1_F) * (sigh2 + sigc2 + C2_F) * (sq2 + C2_F + EPS_F);
                float dmh2 = muh2 - muc2;
                float Un = S[MAPS + 1056 + q] * __fdividef(n2, d2v) - dmh2 * dmh2;
                dacc += Un - S[MAPS + 1408 + q];
            }
        }
    }
#pragma unroll
    for (int o = 16; o; o >>= 1) dacc += __shfl_xor_sync(0xffffffffu, dacc, o);
    if (lane == 0) {
        red[wid] = dacc;
        if (half == 0) Pi[wid >> 1] = pii;
    }
    __syncthreads();

    // ================= P6: block combine + last-block final reduce =========
    if (tid < 16) {
        float cs = (red[2 * tid] + red[2 * tid + 1]) * Pi[tid];
#pragma unroll
        for (int o = 8; o; o >>= 1) cs += __shfl_down_sync(0xffffu, cs, o);
        if (tid == 0) {
            g_part[i] = Sr[0] + cs * (1.0f / 1024.0f);
            __threadfence();
            int t = atomicAdd(&g_done, 1);
            red[0] = (t == 127) ? 1.f : 0.f;
        }
    }
    __syncthreads();

    if (red[0] != 0.f) {
        __threadfence();
        if (tid < 128) {
            float v = g_part[tid];
#pragma unroll
            for (int o = 16; o; o >>= 1) v += __shfl_xor_sync(0xffffffffu, v, o);
            if ((tid & 31) == 0) Pi[tid >> 5] = v;
        }
        __syncthreads();
        if (tid == 0) {
            float A = Pi[0] + Pi[1] + Pi[2] + Pi[3];
            out[0] = -A * (1.0f / 2048.0f);
            g_done = 0;   // reset for next graph replay
        }
    }
}

extern "C" void kernel_launch(void* const* d_in, const int* in_sizes, int n_in,
                              void* d_out, int out_size) {
    const float* prob = (const float*)d_in[0];
    const float* c = (const float*)d_in[1];
    // d_in[2] (z) is unused by the reference.
    float* out = (float*)d_out;
    k_all<<<128, 1024>>>(prob, c, out);
}